// round 9
// baseline (speedup 1.0000x reference)
#include <cuda_runtime.h>
#include <math_constants.h>

#define T_SRC   4096
#define T_DST   4096
#define HID     128
#define NHEADS  8
#define KTOP    128
#define TDENSE  1024
#define NT      768
#define QT      8
#define NW      (NT / 32)
#define NTILES  (T_DST / QT)

#define HPAD      264
#define CAND_CAP  1536
#define C2_CAP    256

#define W_SC    (QT * T_SRC)
#define W_Q     (QT * HID)
#define W_IDX   (QT * KTOP)
#define W_W     (QT * KTOP)
#define W_H3    (QT * HPAD)
#define W_CAND  (QT * CAND_CAP)
#define W_C2    (QT * C2_CAP)
#define W_EQ    KTOP
#define W_CTRL  64
#define W_SEL   (W_H3 + W_CAND + W_C2 + W_EQ + W_CTRL)
#define DYN_BYTES ((W_SC + W_Q + W_IDX + W_W + W_SEL) * 4)

__device__ __forceinline__ unsigned fkey(float f) {
    unsigned b = __float_as_uint(f);
    return b ^ ((b & 0x80000000u) ? 0xFFFFFFFFu : 0x80000000u);
}

__device__ __forceinline__ void ffma2(unsigned long long& acc,
                                      const unsigned long long a,
                                      const unsigned long long b) {
    asm("fma.rn.f32x2 %0, %1, %2, %0;" : "+l"(acc) : "l"(a), "l"(b));
}
__device__ __forceinline__ float hsum2(unsigned long long a) {
    return __uint_as_float((unsigned)a) + __uint_as_float((unsigned)(a >> 32));
}

__device__ __forceinline__ float block_max(float v, float* sred) {
    #pragma unroll
    for (int o = 16; o; o >>= 1) v = fmaxf(v, __shfl_xor_sync(0xFFFFFFFFu, v, o));
    if ((threadIdx.x & 31) == 0) sred[threadIdx.x >> 5] = v;
    __syncthreads();
    if (threadIdx.x < 32) {
        float x = (threadIdx.x < NW) ? sred[threadIdx.x] : -CUDART_INF_F;
        #pragma unroll
        for (int o = 16; o; o >>= 1) x = fmaxf(x, __shfl_xor_sync(0xFFFFFFFFu, x, o));
        if (threadIdx.x == 0) sred[0] = x;
    }
    __syncthreads();
    v = sred[0];
    __syncthreads();
    return v;
}

__device__ __forceinline__ float block_sum(float v, float* sred) {
    #pragma unroll
    for (int o = 16; o; o >>= 1) v += __shfl_xor_sync(0xFFFFFFFFu, v, o);
    if ((threadIdx.x & 31) == 0) sred[threadIdx.x >> 5] = v;
    __syncthreads();
    if (threadIdx.x < 32) {
        float x = (threadIdx.x < NW) ? sred[threadIdx.x] : 0.0f;
        #pragma unroll
        for (int o = 16; o; o >>= 1) x += __shfl_xor_sync(0xFFFFFFFFu, x, o);
        if (threadIdx.x == 0) sred[0] = x;
    }
    __syncthreads();
    v = sred[0];
    __syncthreads();
    return v;
}

__global__ __launch_bounds__(NT, 1)
void tree_attn_r8(const float* __restrict__ q,
                  const float* __restrict__ k,
                  const float* __restrict__ v,
                  float* __restrict__ out) {
    extern __shared__ char smem_raw[];
    float*    s_sc   = (float*)smem_raw;                     // [QT][T_SRC]
    float*    s_q    = s_sc + W_SC;                          // [QT][HID]
    int*      s_idx  = (int*)(s_q + W_Q);                    // [QT][KTOP]
    float*    s_w    = (float*)(s_idx + W_IDX);              // [QT][KTOP]
    unsigned* s_h3   = (unsigned*)(s_w + W_W);               // [QT][HPAD]
    int*      s_cand = (int*)(s_h3 + W_H3);                  // [QT][CAND_CAP]
    int*      s_c2   = (int*)(s_cand + W_CAND);              // [QT][C2_CAP]
    int*      s_eq   = (int*)(s_c2 + W_C2);                  // [KTOP]
    unsigned* s_ctrl = (unsigned*)(s_eq + W_EQ);             // [W_CTRL]
    float*    s_buf  = (float*)s_h3;                         // [NT] union (AV phases)
    unsigned* s_b3   = s_ctrl;            // [8]
    unsigned* s_ngt3 = s_ctrl + 8;        // [8]
    unsigned* s_gtc  = s_ctrl + 16;       // [8]
    unsigned* s_cc   = s_ctrl + 24;       // [8]
    unsigned* s_ovf  = s_ctrl + 32;       // [8]
    unsigned* s_misc = s_ctrl + 40;       // [8]
    float*    s_inv  = (float*)(s_ctrl + 48);  // [8]
    __shared__ float s_redf[NW];

    const int tile = (NTILES - 1) - blockIdx.x;  // longest rows first
    const int h    = blockIdx.y;
    const int tid  = threadIdx.x;
    const int wid  = tid >> 5;
    const int lane = tid & 31;
    const unsigned lmlt = (1u << lane) - 1u;
    const int qi0  = tile * QT;
    const int n_max = qi0 + QT;

    const float* kbase = k + (size_t)h * T_SRC * HID;
    const float* vbase = v + (size_t)h * T_SRC * HID;

    for (int d = tid; d < QT * HID; d += NT)
        s_q[d] = q[((size_t)h * T_DST + qi0) * HID + d];
    __syncthreads();

    // ---- scores: 2 K rows per thread, half-chunk (8-float) stages ----
    float mx[QT];
    #pragma unroll
    for (int s = 0; s < QT; s++) mx[s] = -CUDART_INF_F;

    for (int j0 = 0; j0 < n_max; j0 += 2 * NT) {
        const int jA  = j0 + tid;
        const int jB  = jA + NT;
        const int jAc = (jA < n_max) ? jA : (n_max - 1);
        const int jBc = (jB < n_max) ? jB : (n_max - 1);
        const ulonglong2* krA = (const ulonglong2*)(kbase + (size_t)jAc * HID);
        const ulonglong2* krB = (const ulonglong2*)(kbase + (size_t)jBc * HID);

        unsigned long long accA[QT], accB[QT];
        #pragma unroll
        for (int s = 0; s < QT; s++) { accA[s] = 0ull; accB[s] = 0ull; }

        #pragma unroll 4
        for (int hc = 0; hc < 16; hc++) {          // 16 half-chunks of 8 floats
            ulonglong2 a0 = krA[hc * 2 + 0];
            ulonglong2 a1 = krA[hc * 2 + 1];
            ulonglong2 b0 = krB[hc * 2 + 0];
            ulonglong2 b1 = krB[hc * 2 + 1];
            #pragma unroll
            for (int s = 0; s < QT; s++) {
                const ulonglong2* qp = (const ulonglong2*)(s_q + s * HID + hc * 8);
                ulonglong2 q0 = qp[0];
                ulonglong2 q1 = qp[1];
                ffma2(accA[s], a0.x, q0.x); ffma2(accB[s], b0.x, q0.x);
                ffma2(accA[s], a0.y, q0.y); ffma2(accB[s], b0.y, q0.y);
                ffma2(accA[s], a1.x, q1.x); ffma2(accB[s], b1.x, q1.x);
                ffma2(accA[s], a1.y, q1.y); ffma2(accB[s], b1.y, q1.y);
            }
        }

        #pragma unroll
        for (int s = 0; s < QT; s++) {
            if (jA < n_max) {
                bool ok = (jA <= qi0 + s);
                float sc = ok ? hsum2(accA[s]) : -CUDART_INF_F;
                s_sc[s * T_SRC + jA] = sc;
                mx[s] = fmaxf(mx[s], sc);
            }
            if (jB < n_max) {
                bool ok = (jB <= qi0 + s);
                float sc = ok ? hsum2(accB[s]) : -CUDART_INF_F;
                s_sc[s * T_SRC + jB] = sc;
                mx[s] = fmaxf(mx[s], sc);
            }
        }
    }
    __syncthreads();

    float m[QT];
    #pragma unroll
    for (int s = 0; s < QT; s++) m[s] = block_max(mx[s], s_redf);

    if (qi0 < TDENSE) {
        // ================= dense causal softmax =================
        float psum[QT];
        #pragma unroll
        for (int s = 0; s < QT; s++) psum[s] = 0.0f;
        for (int j = tid; j < n_max; j += NT) {
            #pragma unroll
            for (int s = 0; s < QT; s++) {
                float sc = s_sc[s * T_SRC + j];
                float e = (j <= qi0 + s) ? __expf(sc - m[s]) : 0.0f;
                s_sc[s * T_SRC + j] = e;
                psum[s] += e;
            }
        }
        float inv[QT];
        #pragma unroll
        for (int s = 0; s < QT; s++) inv[s] = 1.0f / block_sum(psum[s], s_redf);

        const int d  = tid & (HID - 1);
        const int qr = tid >> 7;   // 0..5
        float acc[QT];
        #pragma unroll
        for (int s = 0; s < QT; s++) acc[s] = 0.0f;
        for (int j = qr; j < n_max; j += 6) {
            float vv = vbase[(size_t)j * HID + d];
            #pragma unroll
            for (int s = 0; s < QT; s++)
                acc[s] = fmaf(s_sc[s * T_SRC + j], vv, acc[s]);
        }
        #pragma unroll
        for (int s = 0; s < QT; s++) {
            s_buf[tid] = acc[s];
            __syncthreads();
            if (tid < HID) {
                float r = 0.0f;
                #pragma unroll
                for (int p = 0; p < 6; p++) r += s_buf[tid + p * HID];
                out[((size_t)h * T_DST + qi0 + s) * HID + tid] = r * inv[s];
            }
            __syncthreads();
        }
    } else {
        // ================= sparse: exact top-128 =================
        const int bound = ((n_max + NT - 1) / NT) * NT;

        for (int i = tid; i < QT * HPAD; i += NT) s_h3[i] = 0u;
        if (tid < 8) { s_gtc[tid] = 0u; s_cc[tid] = 0u; s_ovf[tid] = 0u; }
        __syncthreads();

        // ---- combined top-byte histogram sweep ----
        for (int j = tid; j < bound; j += NT) {
            #pragma unroll
            for (int s = 0; s < QT; s++) {
                unsigned bin = 256u;
                if (j < n_max) bin = fkey(s_sc[s * T_SRC + j]) >> 24;
                unsigned peers = __match_any_sync(0xFFFFFFFFu, bin);
                if ((__ffs(peers) - 1) == lane)
                    atomicAdd(&s_h3[s * HPAD + bin], (unsigned)__popc(peers));
            }
        }
        __syncthreads();

        // ---- per-warp bin scan (warps 0..7) ----
        if (wid < QT) {
            const int s = wid;
            unsigned g = 0;
            #pragma unroll
            for (int b = 0; b < 8; b++) g += s_h3[s * HPAD + lane * 8 + b];
            unsigned run = g;
            #pragma unroll
            for (int o = 1; o < 32; o <<= 1) {
                unsigned u = __shfl_down_sync(0xFFFFFFFFu, run, o);
                if (lane + o < 32) run += u;
            }
            unsigned S = run - g;
            int found = (run >= KTOP && S < KTOP);
            unsigned bl = 0, acc2 = 0;
            if (found) {
                acc2 = S;
                #pragma unroll 1
                for (int b = 7; b >= 0; b--) {
                    unsigned c = s_h3[s * HPAD + lane * 8 + b];
                    if (acc2 + c >= KTOP) { bl = lane * 8 + b; break; }
                    acc2 += c;
                }
            }
            unsigned fmask = __ballot_sync(0xFFFFFFFFu, found);
            int flane = __ffs(fmask) - 1;
            bl   = __shfl_sync(0xFFFFFFFFu, bl, flane);
            acc2 = __shfl_sync(0xFFFFFFFFu, acc2, flane);
            if (lane == 0) { s_b3[s] = bl; s_ngt3[s] = acc2; }
        }
        __syncthreads();

        // ---- combined compact sweep ----
        for (int j = tid; j < bound; j += NT) {
            #pragma unroll
            for (int s = 0; s < QT; s++) {
                unsigned bin = 257u;
                if (j < n_max) bin = fkey(s_sc[s * T_SRC + j]) >> 24;
                const unsigned b3v = s_b3[s];
                bool gt = (bin > b3v) && (bin <= 255u);
                bool eq = (bin == b3v);
                unsigned mg = __ballot_sync(0xFFFFFFFFu, gt);
                unsigned me = __ballot_sync(0xFFFFFFFFu, eq);
                unsigned baseg = 0, basee = 0;
                if (mg && lane == (unsigned)(__ffs(mg) - 1))
                    baseg = atomicAdd(&s_gtc[s], (unsigned)__popc(mg));
                if (me && lane == (unsigned)(__ffs(me) - 1))
                    basee = atomicAdd(&s_cc[s], (unsigned)__popc(me));
                if (mg) {
                    baseg = __shfl_sync(0xFFFFFFFFu, baseg, __ffs(mg) - 1);
                    if (gt) s_idx[s * KTOP + baseg + __popc(mg & lmlt)] = j;
                }
                if (me) {
                    basee = __shfl_sync(0xFFFFFFFFu, basee, __ffs(me) - 1);
                    if (eq) {
                        unsigned p = basee + __popc(me & lmlt);
                        if (p < CAND_CAP) s_cand[s * CAND_CAP + p] = j;
                    }
                }
            }
        }
        __syncthreads();

        // ---- per-warp refinement (warps 0..7) ----
        if (wid < QT) {
            const int s = wid;
            const float* sc = s_sc + s * T_SRC;
            int nc = (int)s_cc[s];
            unsigned ngt = s_ngt3[s];
            bool ok = (nc <= CAND_CAP);
            int cur = 0;
            int* lists[2] = { s_cand + s * CAND_CAP, s_c2 + s * C2_CAP };
            const int caps[2] = { CAND_CAP, C2_CAP };

            #pragma unroll 1
            for (int lvl = 2; lvl >= 0 && ok; lvl--) {
                const int shift = lvl * 8;
                for (int b = lane; b < 257; b += 32) s_h3[s * HPAD + b] = 0u;
                __syncwarp();
                const int rb = (nc + 31) & ~31;
                for (int i = lane; i < rb; i += 32) {
                    unsigned bin = 256u;
                    if (i < nc) bin = (fkey(sc[lists[cur][i]]) >> shift) & 255u;
                    unsigned peers = __match_any_sync(0xFFFFFFFFu, bin);
                    if ((__ffs(peers) - 1) == lane)
                        s_h3[s * HPAD + bin] += (unsigned)__popc(peers);
                }
                __syncwarp();
                unsigned g = 0;
                #pragma unroll
                for (int b = 0; b < 8; b++) g += s_h3[s * HPAD + lane * 8 + b];
                unsigned run = g;
                #pragma unroll
                for (int o = 1; o < 32; o <<= 1) {
                    unsigned u = __shfl_down_sync(0xFFFFFFFFu, run, o);
                    if (lane + o < 32) run += u;
                }
                unsigned S = run - g;
                int found = (ngt + run >= KTOP && ngt + S < KTOP);
                unsigned bl = 0;
                if (found) {
                    unsigned acc2 = ngt + S;
                    #pragma unroll 1
                    for (int b = 7; b >= 0; b--) {
                        unsigned c = s_h3[s * HPAD + lane * 8 + b];
                        if (acc2 + c >= KTOP) { bl = lane * 8 + b; break; }
                        acc2 += c;
                    }
                }
                unsigned fmask = __ballot_sync(0xFFFFFFFFu, found);
                int flane = __ffs(fmask) - 1;
                bl = __shfl_sync(0xFFFFFFFFu, bl, flane);
                const int dst = cur ^ 1;
                int* dl = lists[dst];
                const int dcap = caps[dst];
                unsigned wg = ngt, we = 0;
                for (int i = lane; i < rb; i += 32) {
                    unsigned bin = 256u; int j = 0;
                    if (i < nc) { j = lists[cur][i]; bin = (fkey(sc[j]) >> shift) & 255u; }
                    bool gt = (bin > bl) && (bin <= 255u);
                    bool eq = (bin == bl);
                    unsigned mg = __ballot_sync(0xFFFFFFFFu, gt);
                    unsigned me = __ballot_sync(0xFFFFFFFFu, eq);
                    if (gt) s_idx[s * KTOP + wg + __popc(mg & lmlt)] = j;
                    if (eq) {
                        unsigned p = we + __popc(me & lmlt);
                        if ((int)p < dcap) dl[p] = j;
                    }
                    wg += __popc(mg); we += __popc(me);
                }
                ngt = wg;
                nc = (int)we;
                cur = dst;
                if (nc > dcap) ok = false;
                __syncwarp();
            }
            if (ok) {
                const int need = KTOP - (int)ngt;
                const int* tl = lists[cur];
                for (int i = lane; i < nc; i += 32) {
                    int ji = tl[i];
                    int rank = 0;
                    for (int m2 = 0; m2 < nc; m2++) rank += (tl[m2] < ji);
                    if (rank < need) s_idx[s * KTOP + (int)ngt + rank] = ji;
                }
            } else if (lane == 0) {
                s_ovf[s] = 1u;
            }
        }
        __syncthreads();

        // ---- rare fallback: full 4-level radix ----
        unsigned ovf_any = 0;
        #pragma unroll
        for (int s = 0; s < QT; s++) ovf_any |= s_ovf[s];
        if (ovf_any) {
            #pragma unroll 1
            for (int s = 0; s < QT; s++) {
                if (!s_ovf[s]) continue;
                const float* sc = s_sc + s * T_SRC;
                unsigned prefix = 0, ngt = 0;
                #pragma unroll 1
                for (int level = 3; level >= 0; level--) {
                    for (int b = tid; b < 257; b += NT) s_h3[b] = 0u;
                    __syncthreads();
                    const unsigned shift = level * 8;
                    const unsigned pmask = (level == 3) ? 0u : (0xFFFFFFFFu << (shift + 8));
                    for (int j = tid; j < bound; j += NT) {
                        unsigned bin = 256u;
                        if (j < n_max) {
                            unsigned key = fkey(sc[j]);
                            if ((key & pmask) == prefix) bin = (key >> shift) & 0xFFu;
                        }
                        unsigned peers = __match_any_sync(0xFFFFFFFFu, bin);
                        if ((__ffs(peers) - 1) == lane)
                            atomicAdd(&s_h3[bin], (unsigned)__popc(peers));
                    }
                    __syncthreads();
                    if (tid < 32) {
                        unsigned g = 0;
                        #pragma unroll
                        for (int b = 0; b < 8; b++) g += s_h3[tid * 8 + b];
                        unsigned run = g;
                        #pragma unroll
                        for (int o = 1; o < 32; o <<= 1) {
                            unsigned u = __shfl_down_sync(0xFFFFFFFFu, run, o);
                            if (tid + o < 32) run += u;
                        }
                        unsigned S = run - g;
                        if (ngt + run >= KTOP && ngt + S < KTOP) {
                            unsigned acc2 = ngt + S;
                            #pragma unroll 1
                            for (int b = 7; b >= 0; b--) {
                                unsigned c = s_h3[tid * 8 + b];
                                if (acc2 + c >= KTOP) {
                                    s_misc[0] = prefix | ((unsigned)(tid * 8 + b) << shift);
                                    s_misc[1] = acc2;
                                    break;
                                }
                                acc2 += c;
                            }
                        }
                    }
                    __syncthreads();
                    prefix = s_misc[0];
                    ngt = s_misc[1];
                    __syncthreads();
                }
                const unsigned t_key = prefix;
                if (tid == 0) { s_misc[2] = 0u; s_misc[3] = 0u; }
                __syncthreads();
                for (int j = tid; j < n_max; j += NT) {
                    unsigned key = fkey(sc[j]);
                    if (key > t_key) {
                        unsigned p = atomicAdd(&s_misc[2], 1u);
                        s_idx[s * KTOP + p] = j;
                    } else if (key == t_key) {
                        unsigned p = atomicAdd(&s_misc[3], 1u);
                        if (p < KTOP) s_eq[p] = j;
                    }
                }
                __syncthreads();
                const int neq = (int)s_misc[3];
                const int need = KTOP - (int)ngt;
                if (need < neq && tid == 0) {
                    int c = (neq < KTOP) ? neq : KTOP;
                    for (int a = 0; a < need; a++) {
                        int mb = a;
                        for (int b = a + 1; b < c; b++)
                            if (s_eq[b] < s_eq[mb]) mb = b;
                        int t2 = s_eq[a]; s_eq[a] = s_eq[mb]; s_eq[mb] = t2;
                    }
                }
                __syncthreads();
                for (int a = tid; a < need; a += NT) s_idx[s * KTOP + (int)ngt + a] = s_eq[a];
                __syncthreads();
            }
        }

        // ---- per-warp softmax weights (warps 0..7) ----
        if (wid < QT) {
            const int s = wid;
            float psum = 0.0f;
            #pragma unroll
            for (int i = 0; i < KTOP / 32; i++) {
                int a = lane + i * 32;
                float e = __expf(s_sc[s * T_SRC + s_idx[s * KTOP + a]] - m[s]);
                s_w[s * KTOP + a] = e;
                psum += e;
            }
            #pragma unroll
            for (int o = 16; o; o >>= 1) psum += __shfl_xor_sync(0xFFFFFFFFu, psum, o);
            if (lane == 0) s_inv[s] = 1.0f / psum;
        }
        __syncthreads();

        // ---- AV over gathered rows ----
        const int d  = tid & (HID - 1);
        const int qr = tid >> 7;   // 0..5
        float acc[QT];
        #pragma unroll
        for (int s = 0; s < QT; s++) acc[s] = 0.0f;
        for (int a = qr; a < KTOP; a += 6) {
            #pragma unroll
            for (int s = 0; s < QT; s++) {
                int j = s_idx[s * KTOP + a];
                acc[s] = fmaf(s_w[s * KTOP + a], vbase[(size_t)j * HID + d], acc[s]);
            }
        }
        #pragma unroll
        for (int s = 0; s < QT; s++) {
            __syncthreads();
            s_buf[tid] = acc[s];
            __syncthreads();
            if (tid < HID) {
                float r = 0.0f;
                #pragma unroll
                for (int p = 0; p < 6; p++) r += s_buf[tid + p * HID];
                out[((size_t)h * T_DST + qi0 + s) * HID + tid] = r * s_inv[s];
            }
        }
    }
}

extern "C" void kernel_launch(void* const* d_in, const int* in_sizes, int n_in,
                              void* d_out, int out_size) {
    const float* q = (const float*)d_in[0];
    const float* k = (const float*)d_in[1];
    const float* v = (const float*)d_in[2];
    float* out = (float*)d_out;

    cudaFuncSetAttribute(tree_attn_r8,
                         cudaFuncAttributeMaxDynamicSharedMemorySize, DYN_BYTES);

    dim3 grid(NTILES, NHEADS);
    tree_attn_r8<<<grid, NT, DYN_BYTES>>>(q, k, v, out);
}

// round 10
// speedup vs baseline: 1.6163x; 1.6163x over previous
#include <cuda_runtime.h>
#include <math_constants.h>

#define T_SRC   4096
#define T_DST   4096
#define HID     128
#define NHEADS  8
#define KTOP    128
#define TDENSE  1024
#define NT      512
#define QT      8
#define NW      (NT / 32)
#define NTILES  (T_DST / QT)
#define NBLK_MAX (T_SRC / 16)   // 256 key-blocks of 16

#define HPAD      264
#define CAND_CAP  1536
#define C2_CAP    256

#define W_SC    (QT * T_SRC)
#define W_Q     (QT * HID)
#define W_IDX   (QT * KTOP)
#define W_W     (QT * KTOP)
#define W_H3    (QT * HPAD)
#define W_CAND  (QT * CAND_CAP)
#define W_C2    (QT * C2_CAP)
#define W_EQ    KTOP
#define W_CTRL  64
#define W_SEL   (W_H3 + W_CAND + W_C2 + W_EQ + W_CTRL)
#define DYN_BYTES ((W_SC + W_Q + W_IDX + W_W + W_SEL) * 4)

// K pre-swizzled into mma A-fragment order: [head][blk][step][lane] float4 (hi and lo)
#define KFRAG_N (NHEADS * NBLK_MAX * 16 * 32)
__device__ float4 g_kfrag_hi[KFRAG_N];
__device__ float4 g_kfrag_lo[KFRAG_N];

__device__ __forceinline__ unsigned fkey(float f) {
    unsigned b = __float_as_uint(f);
    return b ^ ((b & 0x80000000u) ? 0xFFFFFFFFu : 0x80000000u);
}

__device__ __forceinline__ unsigned tf32_hi_bits(float x) {
    return __float_as_uint(x) & 0xFFFFE000u;   // keep sign+exp+10 mantissa bits
}

__device__ __forceinline__ void mma_tf32(float& d0, float& d1, float& d2, float& d3,
                                         unsigned a0, unsigned a1, unsigned a2, unsigned a3,
                                         unsigned b0, unsigned b1) {
    asm volatile(
        "mma.sync.aligned.m16n8k8.row.col.f32.tf32.tf32.f32 "
        "{%0,%1,%2,%3}, {%4,%5,%6,%7}, {%8,%9}, {%0,%1,%2,%3};"
        : "+f"(d0), "+f"(d1), "+f"(d2), "+f"(d3)
        : "r"(a0), "r"(a1), "r"(a2), "r"(a3), "r"(b0), "r"(b1));
}

__device__ __forceinline__ float block_max(float v, float* sred) {
    #pragma unroll
    for (int o = 16; o; o >>= 1) v = fmaxf(v, __shfl_xor_sync(0xFFFFFFFFu, v, o));
    if ((threadIdx.x & 31) == 0) sred[threadIdx.x >> 5] = v;
    __syncthreads();
    if (threadIdx.x < 32) {
        float x = (threadIdx.x < NW) ? sred[threadIdx.x] : -CUDART_INF_F;
        #pragma unroll
        for (int o = 8; o; o >>= 1) x = fmaxf(x, __shfl_xor_sync(0xFFFFFFFFu, x, o));
        if (threadIdx.x == 0) sred[0] = x;
    }
    __syncthreads();
    v = sred[0];
    __syncthreads();
    return v;
}

__device__ __forceinline__ float block_sum(float v, float* sred) {
    #pragma unroll
    for (int o = 16; o; o >>= 1) v += __shfl_xor_sync(0xFFFFFFFFu, v, o);
    if ((threadIdx.x & 31) == 0) sred[threadIdx.x >> 5] = v;
    __syncthreads();
    if (threadIdx.x < 32) {
        float x = (threadIdx.x < NW) ? sred[threadIdx.x] : 0.0f;
        #pragma unroll
        for (int o = 8; o; o >>= 1) x += __shfl_xor_sync(0xFFFFFFFFu, x, o);
        if (threadIdx.x == 0) sred[0] = x;
    }
    __syncthreads();
    v = sred[0];
    __syncthreads();
    return v;
}

// ---- precompute: split K into tf32 hi/lo, laid out in mma fragment order ----
__global__ void split_k_kernel(const float* __restrict__ k) {
    int t = blockIdx.x * blockDim.x + threadIdx.x;   // KFRAG_N threads
    int lane = t & 31;
    int st   = (t >> 5) & 15;
    int blk  = (t >> 9) & (NBLK_MAX - 1);
    int h    = t >> 17;
    int g  = lane >> 2;
    int tg = lane & 3;
    int key = blk * 16 + g;
    int d   = st * 8 + tg;
    const float* kb = k + ((size_t)(h * T_SRC + key)) * HID + d;
    float x0 = kb[0];               // (key,   d)
    float x1 = kb[8 * HID];         // (key+8, d)
    float x2 = kb[4];               // (key,   d+4)
    float x3 = kb[8 * HID + 4];     // (key+8, d+4)
    unsigned h0 = tf32_hi_bits(x0), h1 = tf32_hi_bits(x1);
    unsigned h2 = tf32_hi_bits(x2), h3 = tf32_hi_bits(x3);
    float4 hi = make_float4(__uint_as_float(h0), __uint_as_float(h1),
                            __uint_as_float(h2), __uint_as_float(h3));
    float4 lo = make_float4(x0 - hi.x, x1 - hi.y, x2 - hi.z, x3 - hi.w);
    g_kfrag_hi[t] = hi;
    g_kfrag_lo[t] = lo;
}

__global__ __launch_bounds__(NT, 1)
void tree_attn_r10(const float* __restrict__ q,
                   const float* __restrict__ v,
                   float* __restrict__ out) {
    extern __shared__ char smem_raw[];
    float*    s_sc   = (float*)smem_raw;                     // [QT][T_SRC]
    float*    s_q    = s_sc + W_SC;                          // [QT][HID]
    int*      s_idx  = (int*)(s_q + W_Q);                    // [QT][KTOP]
    float*    s_w    = (float*)(s_idx + W_IDX);              // [QT][KTOP]
    unsigned* s_h3   = (unsigned*)(s_w + W_W);               // [QT][HPAD]
    int*      s_cand = (int*)(s_h3 + W_H3);                  // [QT][CAND_CAP]
    int*      s_c2   = (int*)(s_cand + W_CAND);              // [QT][C2_CAP]
    int*      s_eq   = (int*)(s_c2 + W_C2);                  // [KTOP]
    unsigned* s_ctrl = (unsigned*)(s_eq + W_EQ);             // [W_CTRL]
    float*    s_buf  = (float*)s_h3;                         // [NT] union (AV phases)
    unsigned* s_b3   = s_ctrl;            // [8]
    unsigned* s_ngt3 = s_ctrl + 8;        // [8]
    unsigned* s_gtc  = s_ctrl + 16;       // [8]
    unsigned* s_cc   = s_ctrl + 24;       // [8]
    unsigned* s_ovf  = s_ctrl + 32;       // [8]
    unsigned* s_misc = s_ctrl + 40;       // [8]
    float*    s_inv  = (float*)(s_ctrl + 48);  // [8]
    __shared__ float s_redf[NW];

    const int tile = (NTILES - 1) - blockIdx.x;  // longest rows first
    const int h    = blockIdx.y;
    const int tid  = threadIdx.x;
    const int wid  = tid >> 5;
    const int lane = tid & 31;
    const unsigned lmlt = (1u << lane) - 1u;
    const int qi0  = tile * QT;
    const int n_max = qi0 + QT;

    const float* vbase = v + (size_t)h * T_SRC * HID;

    for (int d = tid; d < QT * HID; d += NT)
        s_q[d] = q[((size_t)h * T_DST + qi0) * HID + d];
    __syncthreads();

    // ---- B (query) fragments: resident in registers for the whole score phase ----
    const int g  = lane >> 2;   // query index 0..7 (n dim)
    const int tg = lane & 3;
    unsigned bh[16][2], bl[16][2];
    #pragma unroll
    for (int st = 0; st < 16; st++) {
        float x0 = s_q[g * HID + st * 8 + tg];
        float x1 = s_q[g * HID + st * 8 + tg + 4];
        unsigned h0 = tf32_hi_bits(x0);
        unsigned h1 = tf32_hi_bits(x1);
        bh[st][0] = h0;
        bh[st][1] = h1;
        bl[st][0] = __float_as_uint(x0 - __uint_as_float(h0));
        bl[st][1] = __float_as_uint(x1 - __uint_as_float(h1));
    }

    // ---- scores via 3xTF32 mma: one 16-key block per warp-iteration ----
    float mx[QT];
    #pragma unroll
    for (int s = 0; s < QT; s++) mx[s] = -CUDART_INF_F;

    const int nblk = (n_max + 15) >> 4;
    for (int blk = wid; blk < nblk; blk += NW) {
        float d0 = 0.f, d1 = 0.f, d2 = 0.f, d3 = 0.f;
        const float4* fh = g_kfrag_hi + ((size_t)(h * NBLK_MAX + blk) * 16) * 32 + lane;
        const float4* fl = g_kfrag_lo + ((size_t)(h * NBLK_MAX + blk) * 16) * 32 + lane;
        #pragma unroll
        for (int st = 0; st < 16; st++) {
            float4 ah4 = fh[st * 32];
            float4 al4 = fl[st * 32];
            unsigned a0 = __float_as_uint(ah4.x), a1 = __float_as_uint(ah4.y);
            unsigned a2 = __float_as_uint(ah4.z), a3 = __float_as_uint(ah4.w);
            unsigned l0 = __float_as_uint(al4.x), l1 = __float_as_uint(al4.y);
            unsigned l2 = __float_as_uint(al4.z), l3 = __float_as_uint(al4.w);
            mma_tf32(d0, d1, d2, d3, a0, a1, a2, a3, bh[st][0], bh[st][1]);  // hi*hi
            mma_tf32(d0, d1, d2, d3, a0, a1, a2, a3, bl[st][0], bl[st][1]);  // hi*lo
            mma_tf32(d0, d1, d2, d3, l0, l1, l2, l3, bh[st][0], bh[st][1]);  // lo*hi
        }
        // D mapping: rows = keys, cols = queries
        const int kA = blk * 16 + g;
        const int kB = kA + 8;
        const int q0 = tg * 2;
        const int q1 = q0 + 1;
        float v0 = (kA <= qi0 + q0) ? d0 : -CUDART_INF_F;
        float v1 = (kA <= qi0 + q1) ? d1 : -CUDART_INF_F;
        float v2 = (kB <= qi0 + q0) ? d2 : -CUDART_INF_F;
        float v3 = (kB <= qi0 + q1) ? d3 : -CUDART_INF_F;
        s_sc[q0 * T_SRC + kA] = v0;
        s_sc[q1 * T_SRC + kA] = v1;
        s_sc[q0 * T_SRC + kB] = v2;
        s_sc[q1 * T_SRC + kB] = v3;
        mx[q0] = fmaxf(mx[q0], fmaxf(v0, v2));
        mx[q1] = fmaxf(mx[q1], fmaxf(v1, v3));
    }
    __syncthreads();

    float m[QT];
    #pragma unroll
    for (int s = 0; s < QT; s++) m[s] = block_max(mx[s], s_redf);

    if (qi0 < TDENSE) {
        // ================= dense causal softmax =================
        float psum[QT];
        #pragma unroll
        for (int s = 0; s < QT; s++) psum[s] = 0.0f;
        for (int j = tid; j < n_max; j += NT) {
            #pragma unroll
            for (int s = 0; s < QT; s++) {
                float sc = s_sc[s * T_SRC + j];
                float e = (j <= qi0 + s) ? __expf(sc - m[s]) : 0.0f;
                s_sc[s * T_SRC + j] = e;
                psum[s] += e;
            }
        }
        float inv[QT];
        #pragma unroll
        for (int s = 0; s < QT; s++) inv[s] = 1.0f / block_sum(psum[s], s_redf);

        const int d  = tid & (HID - 1);
        const int qr = tid >> 7;   // 0..3
        float acc[QT];
        #pragma unroll
        for (int s = 0; s < QT; s++) acc[s] = 0.0f;
        for (int j = qr; j < n_max; j += 4) {
            float vv = vbase[(size_t)j * HID + d];
            #pragma unroll
            for (int s = 0; s < QT; s++)
                acc[s] = fmaf(s_sc[s * T_SRC + j], vv, acc[s]);
        }
        #pragma unroll
        for (int s = 0; s < QT; s++) {
            s_buf[tid] = acc[s];
            __syncthreads();
            if (tid < HID)
                out[((size_t)h * T_DST + qi0 + s) * HID + tid] =
                    (s_buf[tid] + s_buf[tid + HID] + s_buf[tid + 2*HID] + s_buf[tid + 3*HID]) * inv[s];
            __syncthreads();
        }
    } else {
        // ================= sparse: exact top-128 =================
        const int bound = ((n_max + NT - 1) / NT) * NT;

        for (int i = tid; i < QT * HPAD; i += NT) s_h3[i] = 0u;
        if (tid < 8) { s_gtc[tid] = 0u; s_cc[tid] = 0u; s_ovf[tid] = 0u; }
        __syncthreads();

        // ---- combined top-byte histogram sweep ----
        for (int j = tid; j < bound; j += NT) {
            #pragma unroll
            for (int s = 0; s < QT; s++) {
                unsigned bin = 256u;
                if (j < n_max) bin = fkey(s_sc[s * T_SRC + j]) >> 24;
                unsigned peers = __match_any_sync(0xFFFFFFFFu, bin);
                if ((__ffs(peers) - 1) == lane)
                    atomicAdd(&s_h3[s * HPAD + bin], (unsigned)__popc(peers));
            }
        }
        __syncthreads();

        // ---- per-warp bin scan (warps 0..7) ----
        if (wid < QT) {
            const int s = wid;
            unsigned gg = 0;
            #pragma unroll
            for (int b = 0; b < 8; b++) gg += s_h3[s * HPAD + lane * 8 + b];
            unsigned run = gg;
            #pragma unroll
            for (int o = 1; o < 32; o <<= 1) {
                unsigned u = __shfl_down_sync(0xFFFFFFFFu, run, o);
                if (lane + o < 32) run += u;
            }
            unsigned S = run - gg;
            int found = (run >= KTOP && S < KTOP);
            unsigned blb = 0, acc2 = 0;
            if (found) {
                acc2 = S;
                #pragma unroll 1
                for (int b = 7; b >= 0; b--) {
                    unsigned c = s_h3[s * HPAD + lane * 8 + b];
                    if (acc2 + c >= KTOP) { blb = lane * 8 + b; break; }
                    acc2 += c;
                }
            }
            unsigned fmask = __ballot_sync(0xFFFFFFFFu, found);
            int flane = __ffs(fmask) - 1;
            blb  = __shfl_sync(0xFFFFFFFFu, blb, flane);
            acc2 = __shfl_sync(0xFFFFFFFFu, acc2, flane);
            if (lane == 0) { s_b3[s] = blb; s_ngt3[s] = acc2; }
        }
        __syncthreads();

        // ---- combined compact sweep ----
        for (int j = tid; j < bound; j += NT) {
            #pragma unroll
            for (int s = 0; s < QT; s++) {
                unsigned bin = 257u;
                if (j < n_max) bin = fkey(s_sc[s * T_SRC + j]) >> 24;
                const unsigned b3v = s_b3[s];
                bool gt = (bin > b3v) && (bin <= 255u);
                bool eq = (bin == b3v);
                unsigned mg = __ballot_sync(0xFFFFFFFFu, gt);
                unsigned me = __ballot_sync(0xFFFFFFFFu, eq);
                unsigned baseg = 0, basee = 0;
                if (mg && lane == (unsigned)(__ffs(mg) - 1))
                    baseg = atomicAdd(&s_gtc[s], (unsigned)__popc(mg));
                if (me && lane == (unsigned)(__ffs(me) - 1))
                    basee = atomicAdd(&s_cc[s], (unsigned)__popc(me));
                if (mg) {
                    baseg = __shfl_sync(0xFFFFFFFFu, baseg, __ffs(mg) - 1);
                    if (gt) s_idx[s * KTOP + baseg + __popc(mg & lmlt)] = j;
                }
                if (me) {
                    basee = __shfl_sync(0xFFFFFFFFu, basee, __ffs(me) - 1);
                    if (eq) {
                        unsigned p = basee + __popc(me & lmlt);
                        if (p < CAND_CAP) s_cand[s * CAND_CAP + p] = j;
                    }
                }
            }
        }
        __syncthreads();

        // ---- per-warp refinement (warps 0..7) ----
        if (wid < QT) {
            const int s = wid;
            const float* sc = s_sc + s * T_SRC;
            int nc = (int)s_cc[s];
            unsigned ngt = s_ngt3[s];
            bool ok = (nc <= CAND_CAP);
            int cur = 0;
            int* lists[2] = { s_cand + s * CAND_CAP, s_c2 + s * C2_CAP };
            const int caps[2] = { CAND_CAP, C2_CAP };

            #pragma unroll 1
            for (int lvl = 2; lvl >= 0 && ok; lvl--) {
                const int shift = lvl * 8;
                for (int b = lane; b < 257; b += 32) s_h3[s * HPAD + b] = 0u;
                __syncwarp();
                const int rb = (nc + 31) & ~31;
                for (int i = lane; i < rb; i += 32) {
                    unsigned bin = 256u;
                    if (i < nc) bin = (fkey(sc[lists[cur][i]]) >> shift) & 255u;
                    unsigned peers = __match_any_sync(0xFFFFFFFFu, bin);
                    if ((__ffs(peers) - 1) == lane)
                        s_h3[s * HPAD + bin] += (unsigned)__popc(peers);
                }
                __syncwarp();
                unsigned gg = 0;
                #pragma unroll
                for (int b = 0; b < 8; b++) gg += s_h3[s * HPAD + lane * 8 + b];
                unsigned run = gg;
                #pragma unroll
                for (int o = 1; o < 32; o <<= 1) {
                    unsigned u = __shfl_down_sync(0xFFFFFFFFu, run, o);
                    if (lane + o < 32) run += u;
                }
                unsigned S = run - gg;
                int found = (ngt + run >= KTOP && ngt + S < KTOP);
                unsigned blb = 0;
                if (found) {
                    unsigned acc2 = ngt + S;
                    #pragma unroll 1
                    for (int b = 7; b >= 0; b--) {
                        unsigned c = s_h3[s * HPAD + lane * 8 + b];
                        if (acc2 + c >= KTOP) { blb = lane * 8 + b; break; }
                        acc2 += c;
                    }
                }
                unsigned fmask = __ballot_sync(0xFFFFFFFFu, found);
                int flane = __ffs(fmask) - 1;
                blb = __shfl_sync(0xFFFFFFFFu, blb, flane);
                const int dst = cur ^ 1;
                int* dl = lists[dst];
                const int dcap = caps[dst];
                unsigned wg = ngt, we = 0;
                for (int i = lane; i < rb; i += 32) {
                    unsigned bin = 256u; int j = 0;
                    if (i < nc) { j = lists[cur][i]; bin = (fkey(sc[j]) >> shift) & 255u; }
                    bool gt = (bin > blb) && (bin <= 255u);
                    bool eq = (bin == blb);
                    unsigned mg = __ballot_sync(0xFFFFFFFFu, gt);
                    unsigned me = __ballot_sync(0xFFFFFFFFu, eq);
                    if (gt) s_idx[s * KTOP + wg + __popc(mg & lmlt)] = j;
                    if (eq) {
                        unsigned p = we + __popc(me & lmlt);
                        if ((int)p < dcap) dl[p] = j;
                    }
                    wg += __popc(mg); we += __popc(me);
                }
                ngt = wg;
                nc = (int)we;
                cur = dst;
                if (nc > dcap) ok = false;
                __syncwarp();
            }
            if (ok) {
                const int need = KTOP - (int)ngt;
                const int* tl = lists[cur];
                for (int i = lane; i < nc; i += 32) {
                    int ji = tl[i];
                    int rank = 0;
                    for (int m2 = 0; m2 < nc; m2++) rank += (tl[m2] < ji);
                    if (rank < need) s_idx[s * KTOP + (int)ngt + rank] = ji;
                }
            } else if (lane == 0) {
                s_ovf[s] = 1u;
            }
        }
        __syncthreads();

        // ---- rare fallback: full 4-level radix ----
        unsigned ovf_any = 0;
        #pragma unroll
        for (int s = 0; s < QT; s++) ovf_any |= s_ovf[s];
        if (ovf_any) {
            #pragma unroll 1
            for (int s = 0; s < QT; s++) {
                if (!s_ovf[s]) continue;
                const float* sc = s_sc + s * T_SRC;
                unsigned prefix = 0, ngt = 0;
                #pragma unroll 1
                for (int level = 3; level >= 0; level--) {
                    for (int b = tid; b < 257; b += NT) s_h3[b] = 0u;
                    __syncthreads();
                    const unsigned shift = level * 8;
                    const unsigned pmask = (level == 3) ? 0u : (0xFFFFFFFFu << (shift + 8));
                    for (int j = tid; j < bound; j += NT) {
                        unsigned bin = 256u;
                        if (j < n_max) {
                            unsigned key = fkey(sc[j]);
                            if ((key & pmask) == prefix) bin = (key >> shift) & 0xFFu;
                        }
                        unsigned peers = __match_any_sync(0xFFFFFFFFu, bin);
                        if ((__ffs(peers) - 1) == lane)
                            atomicAdd(&s_h3[bin], (unsigned)__popc(peers));
                    }
                    __syncthreads();
                    if (tid < 32) {
                        unsigned gg = 0;
                        #pragma unroll
                        for (int b = 0; b < 8; b++) gg += s_h3[tid * 8 + b];
                        unsigned run = gg;
                        #pragma unroll
                        for (int o = 1; o < 32; o <<= 1) {
                            unsigned u = __shfl_down_sync(0xFFFFFFFFu, run, o);
                            if (tid + o < 32) run += u;
                        }
                        unsigned S = run - gg;
                        if (ngt + run >= KTOP && ngt + S < KTOP) {
                            unsigned acc2 = ngt + S;
                            #pragma unroll 1
                            for (int b = 7; b >= 0; b--) {
                                unsigned c = s_h3[tid * 8 + b];
                                if (acc2 + c >= KTOP) {
                                    s_misc[0] = prefix | ((unsigned)(tid * 8 + b) << shift);
                                    s_misc[1] = acc2;
                                    break;
                                }
                                acc2 += c;
                            }
                        }
                    }
                    __syncthreads();
                    prefix = s_misc[0];
                    ngt = s_misc[1];
                    __syncthreads();
                }
                const unsigned t_key = prefix;
                if (tid == 0) { s_misc[2] = 0u; s_misc[3] = 0u; }
                __syncthreads();
                for (int j = tid; j < n_max; j += NT) {
                    unsigned key = fkey(sc[j]);
                    if (key > t_key) {
                        unsigned p = atomicAdd(&s_misc[2], 1u);
                        s_idx[s * KTOP + p] = j;
                    } else if (key == t_key) {
                        unsigned p = atomicAdd(&s_misc[3], 1u);
                        if (p < KTOP) s_eq[p] = j;
                    }
                }
                __syncthreads();
                const int neq = (int)s_misc[3];
                const int need = KTOP - (int)ngt;
                if (need < neq && tid == 0) {
                    int c = (neq < KTOP) ? neq : KTOP;
                    for (int a = 0; a < need; a++) {
                        int mb = a;
                        for (int b = a + 1; b < c; b++)
                            if (s_eq[b] < s_eq[mb]) mb = b;
                        int t2 = s_eq[a]; s_eq[a] = s_eq[mb]; s_eq[mb] = t2;
                    }
                }
                __syncthreads();
                for (int a = tid; a < need; a += NT) s_idx[s * KTOP + (int)ngt + a] = s_eq[a];
                __syncthreads();
            }
        }

        // ---- per-warp softmax weights (warps 0..7) ----
        if (wid < QT) {
            const int s = wid;
            float psum = 0.0f;
            #pragma unroll
            for (int i = 0; i < KTOP / 32; i++) {
                int a = lane + i * 32;
                float e = __expf(s_sc[s * T_SRC + s_idx[s * KTOP + a]] - m[s]);
                s_w[s * KTOP + a] = e;
                psum += e;
            }
            #pragma unroll
            for (int o = 16; o; o >>= 1) psum += __shfl_xor_sync(0xFFFFFFFFu, psum, o);
            if (lane == 0) s_inv[s] = 1.0f / psum;
        }
        __syncthreads();

        // ---- AV over gathered rows ----
        const int d  = tid & (HID - 1);
        const int qr = tid >> 7;   // 0..3
        float acc[QT];
        #pragma unroll
        for (int s = 0; s < QT; s++) acc[s] = 0.0f;
        for (int a = qr; a < KTOP; a += 4) {
            #pragma unroll
            for (int s = 0; s < QT; s++) {
                int j = s_idx[s * KTOP + a];
                acc[s] = fmaf(s_w[s * KTOP + a], vbase[(size_t)j * HID + d], acc[s]);
            }
        }
        #pragma unroll
        for (int s = 0; s < QT; s++) {
            __syncthreads();
            s_buf[tid] = acc[s];
            __syncthreads();
            if (tid < HID)
                out[((size_t)h * T_DST + qi0 + s) * HID + tid] =
                    (s_buf[tid] + s_buf[tid + HID] + s_buf[tid + 2*HID] + s_buf[tid + 3*HID]) * s_inv[s];
        }
    }
}

extern "C" void kernel_launch(void* const* d_in, const int* in_sizes, int n_in,
                              void* d_out, int out_size) {
    const float* q = (const float*)d_in[0];
    const float* k = (const float*)d_in[1];
    const float* v = (const float*)d_in[2];
    float* out = (float*)d_out;

    split_k_kernel<<<KFRAG_N / 256, 256>>>(k);

    cudaFuncSetAttribute(tree_attn_r10,
                         cudaFuncAttributeMaxDynamicSharedMemorySize, DYN_BYTES);

    dim3 grid(NTILES, NHEADS);
    tree_attn_r10<<<grid, NT, DYN_BYTES>>>(q, v, out);
}

// round 11
// speedup vs baseline: 1.9900x; 1.2312x over previous
#include <cuda_runtime.h>
#include <math_constants.h>

#define T_SRC   4096
#define T_DST   4096
#define HID     128
#define NHEADS  8
#define KTOP    128
#define TDENSE  1024
#define NT      512
#define QT      8
#define NW      (NT / 32)
#define NTILES  (T_DST / QT)
#define NBLK_MAX (T_SRC / 16)   // 256 key-blocks of 16

#define HPAD      264
#define CAND_CAP  1536
#define C2_CAP    256

#define W_SC    (QT * T_SRC)
#define W_Q     (QT * HID)
#define W_IDX   (QT * KTOP)
#define W_W     (QT * KTOP)
#define W_H3    (QT * HPAD)
#define W_CAND  (QT * CAND_CAP)
#define W_C2    (QT * C2_CAP)
#define W_EQ    KTOP
#define W_CTRL  64
#define W_SEL   (W_H3 + W_CAND + W_C2 + W_EQ + W_CTRL)
#define DYN_BYTES ((W_SC + W_Q + W_IDX + W_W + W_SEL) * 4)

// K pre-swizzled into mma A-fragment order (raw floats; hi/lo split done in-kernel)
#define KFRAG_N (NHEADS * NBLK_MAX * 16 * 32)
__device__ float4 g_kfrag[KFRAG_N];

__device__ __forceinline__ unsigned fkey(float f) {
    unsigned b = __float_as_uint(f);
    return b ^ ((b & 0x80000000u) ? 0xFFFFFFFFu : 0x80000000u);
}

__device__ __forceinline__ unsigned tf32_hi_bits(float x) {
    return __float_as_uint(x) & 0xFFFFE000u;
}

__device__ __forceinline__ void mma_tf32(float& d0, float& d1, float& d2, float& d3,
                                         unsigned a0, unsigned a1, unsigned a2, unsigned a3,
                                         unsigned b0, unsigned b1) {
    asm volatile(
        "mma.sync.aligned.m16n8k8.row.col.f32.tf32.tf32.f32 "
        "{%0,%1,%2,%3}, {%4,%5,%6,%7}, {%8,%9}, {%0,%1,%2,%3};"
        : "+f"(d0), "+f"(d1), "+f"(d2), "+f"(d3)
        : "r"(a0), "r"(a1), "r"(a2), "r"(a3), "r"(b0), "r"(b1));
}

__device__ __forceinline__ float block_max(float v, float* sred) {
    #pragma unroll
    for (int o = 16; o; o >>= 1) v = fmaxf(v, __shfl_xor_sync(0xFFFFFFFFu, v, o));
    if ((threadIdx.x & 31) == 0) sred[threadIdx.x >> 5] = v;
    __syncthreads();
    if (threadIdx.x < 32) {
        float x = (threadIdx.x < NW) ? sred[threadIdx.x] : -CUDART_INF_F;
        #pragma unroll
        for (int o = 8; o; o >>= 1) x = fmaxf(x, __shfl_xor_sync(0xFFFFFFFFu, x, o));
        if (threadIdx.x == 0) sred[0] = x;
    }
    __syncthreads();
    v = sred[0];
    __syncthreads();
    return v;
}

__device__ __forceinline__ float block_sum(float v, float* sred) {
    #pragma unroll
    for (int o = 16; o; o >>= 1) v += __shfl_xor_sync(0xFFFFFFFFu, v, o);
    if ((threadIdx.x & 31) == 0) sred[threadIdx.x >> 5] = v;
    __syncthreads();
    if (threadIdx.x < 32) {
        float x = (threadIdx.x < NW) ? sred[threadIdx.x] : 0.0f;
        #pragma unroll
        for (int o = 8; o; o >>= 1) x += __shfl_xor_sync(0xFFFFFFFFu, x, o);
        if (threadIdx.x == 0) sred[0] = x;
    }
    __syncthreads();
    v = sred[0];
    __syncthreads();
    return v;
}

// ---- precompute: K in mma fragment order ----
__global__ void swizzle_k_kernel(const float* __restrict__ k) {
    int t = blockIdx.x * blockDim.x + threadIdx.x;
    int lane = t & 31;
    int st   = (t >> 5) & 15;
    int blk  = (t >> 9) & (NBLK_MAX - 1);
    int h    = t >> 17;
    int g  = lane >> 2;
    int tg = lane & 3;
    int key = blk * 16 + g;
    int d   = st * 8 + tg;
    const float* kb = k + ((size_t)(h * T_SRC + key)) * HID + d;
    g_kfrag[t] = make_float4(kb[0], kb[8 * HID], kb[4], kb[8 * HID + 4]);
}

__global__ __launch_bounds__(NT, 1)
void tree_attn_r11(const float* __restrict__ q,
                   const float* __restrict__ v,
                   float* __restrict__ out) {
    extern __shared__ char smem_raw[];
    float*    s_sc   = (float*)smem_raw;                     // [QT][T_SRC]
    float*    s_q    = s_sc + W_SC;                          // [QT][HID]
    int*      s_idx  = (int*)(s_q + W_Q);                    // [QT][KTOP]
    float*    s_w    = (float*)(s_idx + W_IDX);              // [QT][KTOP]
    unsigned* s_h3   = (unsigned*)(s_w + W_W);               // [QT][HPAD]
    int*      s_cand = (int*)(s_h3 + W_H3);                  // [QT][CAND_CAP]
    int*      s_c2   = (int*)(s_cand + W_CAND);              // [QT][C2_CAP]
    int*      s_eq   = (int*)(s_c2 + W_C2);                  // [KTOP]
    unsigned* s_ctrl = (unsigned*)(s_eq + W_EQ);             // [W_CTRL]
    float*    s_buf  = (float*)s_h3;                         // [NT] union (AV phases)
    unsigned* s_b3   = s_ctrl;            // [8]
    unsigned* s_ngt3 = s_ctrl + 8;        // [8]
    unsigned* s_gtc  = s_ctrl + 16;       // [8]
    unsigned* s_cc   = s_ctrl + 24;       // [8]
    unsigned* s_ovf  = s_ctrl + 32;       // [8]
    unsigned* s_misc = s_ctrl + 40;       // [8]
    float*    s_inv  = (float*)(s_ctrl + 48);  // [8]
    __shared__ float s_redf[NW];

    const int tile = (NTILES - 1) - blockIdx.x;  // longest rows first
    const int h    = blockIdx.y;
    const int tid  = threadIdx.x;
    const int wid  = tid >> 5;
    const int lane = tid & 31;
    const unsigned lmlt = (1u << lane) - 1u;
    const int qi0  = tile * QT;
    const int n_max = qi0 + QT;
    const bool sparse = (qi0 >= TDENSE);

    const float* vbase = v + (size_t)h * T_SRC * HID;

    for (int d = tid; d < QT * HID; d += NT)
        s_q[d] = q[((size_t)h * T_DST + qi0) * HID + d];
    if (sparse) {
        for (int i = tid; i < QT * HPAD; i += NT) s_h3[i] = 0u;
        if (tid < 8) { s_gtc[tid] = 0u; s_cc[tid] = 0u; s_ovf[tid] = 0u; }
    }
    __syncthreads();

    // ---- B (query) fragments: resident in registers ----
    const int g  = lane >> 2;   // 0..7
    const int tg = lane & 3;
    unsigned bh[16][2], bl[16][2];
    #pragma unroll
    for (int st = 0; st < 16; st++) {
        float x0 = s_q[g * HID + st * 8 + tg];
        float x1 = s_q[g * HID + st * 8 + tg + 4];
        unsigned h0 = tf32_hi_bits(x0);
        unsigned h1 = tf32_hi_bits(x1);
        bh[st][0] = h0;
        bh[st][1] = h1;
        bl[st][0] = __float_as_uint(x0 - __uint_as_float(h0));
        bl[st][1] = __float_as_uint(x1 - __uint_as_float(h1));
    }

    // ---- scores via 3xTF32 mma, in-register hi/lo split, fused histogram ----
    float mx[QT];
    #pragma unroll
    for (int s = 0; s < QT; s++) mx[s] = -CUDART_INF_F;

    const int nblk = (n_max + 15) >> 4;
    for (int blk = wid; blk < nblk; blk += NW) {
        float d0 = 0.f, d1 = 0.f, d2 = 0.f, d3 = 0.f;
        const float4* fk = g_kfrag + ((size_t)(h * NBLK_MAX + blk) * 16) * 32 + lane;
        #pragma unroll
        for (int st = 0; st < 16; st++) {
            float4 a4 = fk[st * 32];
            unsigned a0 = tf32_hi_bits(a4.x), a1 = tf32_hi_bits(a4.y);
            unsigned a2 = tf32_hi_bits(a4.z), a3 = tf32_hi_bits(a4.w);
            unsigned l0 = __float_as_uint(a4.x - __uint_as_float(a0));
            unsigned l1 = __float_as_uint(a4.y - __uint_as_float(a1));
            unsigned l2 = __float_as_uint(a4.z - __uint_as_float(a2));
            unsigned l3 = __float_as_uint(a4.w - __uint_as_float(a3));
            mma_tf32(d0, d1, d2, d3, a0, a1, a2, a3, bh[st][0], bh[st][1]);  // hi*hi
            mma_tf32(d0, d1, d2, d3, a0, a1, a2, a3, bl[st][0], bl[st][1]);  // hi*lo
            mma_tf32(d0, d1, d2, d3, l0, l1, l2, l3, bh[st][0], bh[st][1]);  // lo*hi
        }
        const int kA = blk * 16 + g;
        const int kB = kA + 8;
        const int q0 = tg * 2;
        const int q1 = q0 + 1;
        float v0 = (kA <= qi0 + q0) ? d0 : -CUDART_INF_F;
        float v1 = (kA <= qi0 + q1) ? d1 : -CUDART_INF_F;
        float v2 = (kB <= qi0 + q0) ? d2 : -CUDART_INF_F;
        float v3 = (kB <= qi0 + q1) ? d3 : -CUDART_INF_F;
        s_sc[q0 * T_SRC + kA] = v0;
        s_sc[q1 * T_SRC + kA] = v1;
        s_sc[q0 * T_SRC + kB] = v2;
        s_sc[q1 * T_SRC + kB] = v3;
        mx[q0] = fmaxf(mx[q0], fmaxf(v0, v2));
        mx[q1] = fmaxf(mx[q1], fmaxf(v1, v3));
        if (sparse) {
            // fused top-byte histogram (masked/padded scores land in bin 0: harmless)
            atomicAdd(&s_h3[q0 * HPAD + (fkey(v0) >> 24)], 1u);
            atomicAdd(&s_h3[q1 * HPAD + (fkey(v1) >> 24)], 1u);
            atomicAdd(&s_h3[q0 * HPAD + (fkey(v2) >> 24)], 1u);
            atomicAdd(&s_h3[q1 * HPAD + (fkey(v3) >> 24)], 1u);
        }
    }
    __syncthreads();

    float m[QT];
    #pragma unroll
    for (int s = 0; s < QT; s++) m[s] = block_max(mx[s], s_redf);

    if (!sparse) {
        // ================= dense causal softmax =================
        float psum[QT];
        #pragma unroll
        for (int s = 0; s < QT; s++) psum[s] = 0.0f;
        for (int j = tid; j < n_max; j += NT) {
            #pragma unroll
            for (int s = 0; s < QT; s++) {
                float sc = s_sc[s * T_SRC + j];
                float e = (j <= qi0 + s) ? __expf(sc - m[s]) : 0.0f;
                s_sc[s * T_SRC + j] = e;
                psum[s] += e;
            }
        }
        float inv[QT];
        #pragma unroll
        for (int s = 0; s < QT; s++) inv[s] = 1.0f / block_sum(psum[s], s_redf);

        const int d  = tid & (HID - 1);
        const int qr = tid >> 7;   // 0..3
        float acc[QT];
        #pragma unroll
        for (int s = 0; s < QT; s++) acc[s] = 0.0f;
        for (int j = qr; j < n_max; j += 4) {
            float vv = vbase[(size_t)j * HID + d];
            #pragma unroll
            for (int s = 0; s < QT; s++)
                acc[s] = fmaf(s_sc[s * T_SRC + j], vv, acc[s]);
        }
        #pragma unroll
        for (int s = 0; s < QT; s++) {
            s_buf[tid] = acc[s];
            __syncthreads();
            if (tid < HID)
                out[((size_t)h * T_DST + qi0 + s) * HID + tid] =
                    (s_buf[tid] + s_buf[tid + HID] + s_buf[tid + 2*HID] + s_buf[tid + 3*HID]) * inv[s];
            __syncthreads();
        }
    } else {
        // ================= sparse: exact top-128 =================
        const int bound = ((n_max + NT - 1) / NT) * NT;

        // ---- per-warp bin scan (warps 0..7); histogram already built ----
        if (wid < QT) {
            const int s = wid;
            unsigned gg = 0;
            #pragma unroll
            for (int b = 0; b < 8; b++) gg += s_h3[s * HPAD + lane * 8 + b];
            unsigned run = gg;
            #pragma unroll
            for (int o = 1; o < 32; o <<= 1) {
                unsigned u = __shfl_down_sync(0xFFFFFFFFu, run, o);
                if (lane + o < 32) run += u;
            }
            unsigned S = run - gg;
            int found = (run >= KTOP && S < KTOP);
            unsigned blb = 0, acc2 = 0;
            if (found) {
                acc2 = S;
                #pragma unroll 1
                for (int b = 7; b >= 0; b--) {
                    unsigned c = s_h3[s * HPAD + lane * 8 + b];
                    if (acc2 + c >= KTOP) { blb = lane * 8 + b; break; }
                    acc2 += c;
                }
            }
            unsigned fmask = __ballot_sync(0xFFFFFFFFu, found);
            int flane = __ffs(fmask) - 1;
            blb  = __shfl_sync(0xFFFFFFFFu, blb, flane);
            acc2 = __shfl_sync(0xFFFFFFFFu, acc2, flane);
            if (lane == 0) { s_b3[s] = blb; s_ngt3[s] = acc2; }
        }
        __syncthreads();

        // ---- combined compact sweep ----
        for (int j = tid; j < bound; j += NT) {
            #pragma unroll
            for (int s = 0; s < QT; s++) {
                unsigned bin = 257u;
                if (j < n_max) bin = fkey(s_sc[s * T_SRC + j]) >> 24;
                const unsigned b3v = s_b3[s];
                bool gt = (bin > b3v) && (bin <= 255u);
                bool eq = (bin == b3v);
                unsigned mg = __ballot_sync(0xFFFFFFFFu, gt);
                unsigned me = __ballot_sync(0xFFFFFFFFu, eq);
                unsigned baseg = 0, basee = 0;
                if (mg && lane == (unsigned)(__ffs(mg) - 1))
                    baseg = atomicAdd(&s_gtc[s], (unsigned)__popc(mg));
                if (me && lane == (unsigned)(__ffs(me) - 1))
                    basee = atomicAdd(&s_cc[s], (unsigned)__popc(me));
                if (mg) {
                    baseg = __shfl_sync(0xFFFFFFFFu, baseg, __ffs(mg) - 1);
                    if (gt) s_idx[s * KTOP + baseg + __popc(mg & lmlt)] = j;
                }
                if (me) {
                    basee = __shfl_sync(0xFFFFFFFFu, basee, __ffs(me) - 1);
                    if (eq) {
                        unsigned p = basee + __popc(me & lmlt);
                        if (p < CAND_CAP) s_cand[s * CAND_CAP + p] = j;
                    }
                }
            }
        }
        __syncthreads();

        // ---- per-warp refinement (warps 0..7) ----
        if (wid < QT) {
            const int s = wid;
            const float* sc = s_sc + s * T_SRC;
            int nc = (int)s_cc[s];
            unsigned ngt = s_ngt3[s];
            bool ok = (nc <= CAND_CAP);
            int cur = 0;
            int* lists[2] = { s_cand + s * CAND_CAP, s_c2 + s * C2_CAP };
            const int caps[2] = { CAND_CAP, C2_CAP };

            #pragma unroll 1
            for (int lvl = 2; lvl >= 0 && ok; lvl--) {
                const int shift = lvl * 8;
                for (int b = lane; b < 257; b += 32) s_h3[s * HPAD + b] = 0u;
                __syncwarp();
                const int rb = (nc + 31) & ~31;
                for (int i = lane; i < rb; i += 32) {
                    unsigned bin = 256u;
                    if (i < nc) bin = (fkey(sc[lists[cur][i]]) >> shift) & 255u;
                    unsigned peers = __match_any_sync(0xFFFFFFFFu, bin);
                    if ((__ffs(peers) - 1) == lane)
                        s_h3[s * HPAD + bin] += (unsigned)__popc(peers);
                }
                __syncwarp();
                unsigned gg = 0;
                #pragma unroll
                for (int b = 0; b < 8; b++) gg += s_h3[s * HPAD + lane * 8 + b];
                unsigned run = gg;
                #pragma unroll
                for (int o = 1; o < 32; o <<= 1) {
                    unsigned u = __shfl_down_sync(0xFFFFFFFFu, run, o);
                    if (lane + o < 32) run += u;
                }
                unsigned S = run - gg;
                int found = (ngt + run >= KTOP && ngt + S < KTOP);
                unsigned blb = 0;
                if (found) {
                    unsigned acc2 = ngt + S;
                    #pragma unroll 1
                    for (int b = 7; b >= 0; b--) {
                        unsigned c = s_h3[s * HPAD + lane * 8 + b];
                        if (acc2 + c >= KTOP) { blb = lane * 8 + b; break; }
                        acc2 += c;
                    }
                }
                unsigned fmask = __ballot_sync(0xFFFFFFFFu, found);
                int flane = __ffs(fmask) - 1;
                blb = __shfl_sync(0xFFFFFFFFu, blb, flane);
                const int dst = cur ^ 1;
                int* dl = lists[dst];
                const int dcap = caps[dst];
                unsigned wg = ngt, we = 0;
                for (int i = lane; i < rb; i += 32) {
                    unsigned bin = 256u; int j = 0;
                    if (i < nc) { j = lists[cur][i]; bin = (fkey(sc[j]) >> shift) & 255u; }
                    bool gt = (bin > blb) && (bin <= 255u);
                    bool eq = (bin == blb);
                    unsigned mg = __ballot_sync(0xFFFFFFFFu, gt);
                    unsigned me = __ballot_sync(0xFFFFFFFFu, eq);
                    if (gt) s_idx[s * KTOP + wg + __popc(mg & lmlt)] = j;
                    if (eq) {
                        unsigned p = we + __popc(me & lmlt);
                        if ((int)p < dcap) dl[p] = j;
                    }
                    wg += __popc(mg); we += __popc(me);
                }
                ngt = wg;
                nc = (int)we;
                cur = dst;
                if (nc > dcap) ok = false;
                __syncwarp();
            }
            if (ok) {
                const int need = KTOP - (int)ngt;
                const int* tl = lists[cur];
                for (int i = lane; i < nc; i += 32) {
                    int ji = tl[i];
                    int rank = 0;
                    for (int m2 = 0; m2 < nc; m2++) rank += (tl[m2] < ji);
                    if (rank < need) s_idx[s * KTOP + (int)ngt + rank] = ji;
                }
            } else if (lane == 0) {
                s_ovf[s] = 1u;
            }
        }
        __syncthreads();

        // ---- rare fallback: full 4-level radix ----
        unsigned ovf_any = 0;
        #pragma unroll
        for (int s = 0; s < QT; s++) ovf_any |= s_ovf[s];
        if (ovf_any) {
            #pragma unroll 1
            for (int s = 0; s < QT; s++) {
                if (!s_ovf[s]) continue;
                const float* sc = s_sc + s * T_SRC;
                unsigned prefix = 0, ngt = 0;
                #pragma unroll 1
                for (int level = 3; level >= 0; level--) {
                    for (int b = tid; b < 257; b += NT) s_h3[b] = 0u;
                    __syncthreads();
                    const unsigned shift = level * 8;
                    const unsigned pmask = (level == 3) ? 0u : (0xFFFFFFFFu << (shift + 8));
                    for (int j = tid; j < bound; j += NT) {
                        unsigned bin = 256u;
                        if (j < n_max) {
                            unsigned key = fkey(sc[j]);
                            if ((key & pmask) == prefix) bin = (key >> shift) & 0xFFu;
                        }
                        unsigned peers = __match_any_sync(0xFFFFFFFFu, bin);
                        if ((__ffs(peers) - 1) == lane)
                            atomicAdd(&s_h3[bin], (unsigned)__popc(peers));
                    }
                    __syncthreads();
                    if (tid < 32) {
                        unsigned gg = 0;
                        #pragma unroll
                        for (int b = 0; b < 8; b++) gg += s_h3[tid * 8 + b];
                        unsigned run = gg;
                        #pragma unroll
                        for (int o = 1; o < 32; o <<= 1) {
                            unsigned u = __shfl_down_sync(0xFFFFFFFFu, run, o);
                            if (tid + o < 32) run += u;
                        }
                        unsigned S = run - gg;
                        if (ngt + run >= KTOP && ngt + S < KTOP) {
                            unsigned acc2 = ngt + S;
                            #pragma unroll 1
                            for (int b = 7; b >= 0; b--) {
                                unsigned c = s_h3[tid * 8 + b];
                                if (acc2 + c >= KTOP) {
                                    s_misc[0] = prefix | ((unsigned)(tid * 8 + b) << shift);
                                    s_misc[1] = acc2;
                                    break;
                                }
                                acc2 += c;
                            }
                        }
                    }
                    __syncthreads();
                    prefix = s_misc[0];
                    ngt = s_misc[1];
                    __syncthreads();
                }
                const unsigned t_key = prefix;
                if (tid == 0) { s_misc[2] = 0u; s_misc[3] = 0u; }
                __syncthreads();
                for (int j = tid; j < n_max; j += NT) {
                    unsigned key = fkey(sc[j]);
                    if (key > t_key) {
                        unsigned p = atomicAdd(&s_misc[2], 1u);
                        s_idx[s * KTOP + p] = j;
                    } else if (key == t_key) {
                        unsigned p = atomicAdd(&s_misc[3], 1u);
                        if (p < KTOP) s_eq[p] = j;
                    }
                }
                __syncthreads();
                const int neq = (int)s_misc[3];
                const int need = KTOP - (int)ngt;
                if (need < neq && tid == 0) {
                    int c = (neq < KTOP) ? neq : KTOP;
                    for (int a = 0; a < need; a++) {
                        int mb = a;
                        for (int b = a + 1; b < c; b++)
                            if (s_eq[b] < s_eq[mb]) mb = b;
                        int t2 = s_eq[a]; s_eq[a] = s_eq[mb]; s_eq[mb] = t2;
                    }
                }
                __syncthreads();
                for (int a = tid; a < need; a += NT) s_idx[s * KTOP + (int)ngt + a] = s_eq[a];
                __syncthreads();
            }
        }

        // ---- per-warp softmax weights (warps 0..7) ----
        if (wid < QT) {
            const int s = wid;
            float psum = 0.0f;
            #pragma unroll
            for (int i = 0; i < KTOP / 32; i++) {
                int a = lane + i * 32;
                float e = __expf(s_sc[s * T_SRC + s_idx[s * KTOP + a]] - m[s]);
                s_w[s * KTOP + a] = e;
                psum += e;
            }
            #pragma unroll
            for (int o = 16; o; o >>= 1) psum += __shfl_xor_sync(0xFFFFFFFFu, psum, o);
            if (lane == 0) s_inv[s] = 1.0f / psum;
        }
        __syncthreads();

        // ---- AV over gathered rows ----
        const int d  = tid & (HID - 1);
        const int qr = tid >> 7;   // 0..3
        float acc[QT];
        #pragma unroll
        for (int s = 0; s < QT; s++) acc[s] = 0.0f;
        for (int a = qr; a < KTOP; a += 4) {
            #pragma unroll
            for (int s = 0; s < QT; s++) {
                int j = s_idx[s * KTOP + a];
                acc[s] = fmaf(s_w[s * KTOP + a], vbase[(size_t)j * HID + d], acc[s]);
            }
        }
        #pragma unroll
        for (int s = 0; s < QT; s++) {
            __syncthreads();
            s_buf[tid] = acc[s];
            __syncthreads();
            if (tid < HID)
                out[((size_t)h * T_DST + qi0 + s) * HID + tid] =
                    (s_buf[tid] + s_buf[tid + HID] + s_buf[tid + 2*HID] + s_buf[tid + 3*HID]) * s_inv[s];
        }
    }
}

extern "C" void kernel_launch(void* const* d_in, const int* in_sizes, int n_in,
                              void* d_out, int out_size) {
    const float* q = (const float*)d_in[0];
    const float* k = (const float*)d_in[1];
    const float* v = (const float*)d_in[2];
    float* out = (float*)d_out;

    swizzle_k_kernel<<<KFRAG_N / 256, 256>>>(k);

    cudaFuncSetAttribute(tree_attn_r11,
                         cudaFuncAttributeMaxDynamicSharedMemorySize, DYN_BYTES);

    dim3 grid(NTILES, NHEADS);
    tree_attn_r11<<<grid, NT, DYN_BYTES>>>(q, v, out);
}

// round 13
// speedup vs baseline: 2.0191x; 1.0146x over previous
#include <cuda_runtime.h>
#include <math_constants.h>

#define T_SRC   4096
#define T_DST   4096
#define HID     128
#define NHEADS  8
#define KTOP    128
#define TDENSE  1024
#define NT      512
#define QT      8
#define NW      (NT / 32)
#define NTILES  (T_DST / QT)
#define NBLK_MAX (T_SRC / 16)   // 256 key-blocks of 16
#define NJBLK    (T_SRC / 8)    // 512 key-chunks of 8 (V frags)
#define NDTILE   (HID / 16)     // 8 d-tiles of 16

#define HPAD      264
#define CAND_CAP  1536
#define C2_CAP    256

#define W_SC    (QT * T_SRC)
#define W_Q     (QT * HID)
#define W_IDX   (QT * KTOP)
#define W_W     (QT * KTOP)
#define W_H3    (QT * HPAD)
#define W_CAND  (QT * CAND_CAP)
#define W_C2    (QT * C2_CAP)
#define W_EQ    KTOP
#define W_CTRL  64
#define W_SEL   (W_H3 + W_CAND + W_C2 + W_EQ + W_CTRL)
#define DYN_BYTES ((W_SC + W_Q + W_IDX + W_W + W_SEL) * 4)

// K pre-swizzled into mma A-fragment order (raw floats; hi/lo split in-kernel)
#define KFRAG_N (NHEADS * NBLK_MAX * 16 * 32)
__device__ float4 g_kfrag[KFRAG_N];
// V^T pre-swizzled into mma A-fragment order: [head][dtile][jblk][lane]
#define VFRAG_N (NHEADS * NDTILE * NJBLK * 32)
__device__ float4 g_vfrag[VFRAG_N];

__device__ __forceinline__ unsigned fkey(float f) {
    unsigned b = __float_as_uint(f);
    return b ^ ((b & 0x80000000u) ? 0xFFFFFFFFu : 0x80000000u);
}

__device__ __forceinline__ unsigned tf32_hi_bits(float x) {
    return __float_as_uint(x) & 0xFFFFE000u;
}

__device__ __forceinline__ void mma_tf32(float& d0, float& d1, float& d2, float& d3,
                                         unsigned a0, unsigned a1, unsigned a2, unsigned a3,
                                         unsigned b0, unsigned b1) {
    asm volatile(
        "mma.sync.aligned.m16n8k8.row.col.f32.tf32.tf32.f32 "
        "{%0,%1,%2,%3}, {%4,%5,%6,%7}, {%8,%9}, {%0,%1,%2,%3};"
        : "+f"(d0), "+f"(d1), "+f"(d2), "+f"(d3)
        : "r"(a0), "r"(a1), "r"(a2), "r"(a3), "r"(b0), "r"(b1));
}

__device__ __forceinline__ float block_max(float v, float* sred) {
    #pragma unroll
    for (int o = 16; o; o >>= 1) v = fmaxf(v, __shfl_xor_sync(0xFFFFFFFFu, v, o));
    if ((threadIdx.x & 31) == 0) sred[threadIdx.x >> 5] = v;
    __syncthreads();
    if (threadIdx.x < 32) {
        float x = (threadIdx.x < NW) ? sred[threadIdx.x] : -CUDART_INF_F;
        #pragma unroll
        for (int o = 8; o; o >>= 1) x = fmaxf(x, __shfl_xor_sync(0xFFFFFFFFu, x, o));
        if (threadIdx.x == 0) sred[0] = x;
    }
    __syncthreads();
    v = sred[0];
    __syncthreads();
    return v;
}

__device__ __forceinline__ float block_sum(float v, float* sred) {
    #pragma unroll
    for (int o = 16; o; o >>= 1) v += __shfl_xor_sync(0xFFFFFFFFu, v, o);
    if ((threadIdx.x & 31) == 0) sred[threadIdx.x >> 5] = v;
    __syncthreads();
    if (threadIdx.x < 32) {
        float x = (threadIdx.x < NW) ? sred[threadIdx.x] : 0.0f;
        #pragma unroll
        for (int o = 8; o; o >>= 1) x += __shfl_xor_sync(0xFFFFFFFFu, x, o);
        if (threadIdx.x == 0) sred[0] = x;
    }
    __syncthreads();
    v = sred[0];
    __syncthreads();
    return v;
}

// ---- precompute: K in mma fragment order ----
__global__ void swizzle_k_kernel(const float* __restrict__ k) {
    int t = blockIdx.x * blockDim.x + threadIdx.x;
    int lane = t & 31;
    int st   = (t >> 5) & 15;
    int blk  = (t >> 9) & (NBLK_MAX - 1);
    int h    = t >> 17;
    int g  = lane >> 2;
    int tg = lane & 3;
    int key = blk * 16 + g;
    int d   = st * 8 + tg;
    const float* kb = k + ((size_t)(h * T_SRC + key)) * HID + d;
    g_kfrag[t] = make_float4(kb[0], kb[8 * HID], kb[4], kb[8 * HID + 4]);
}

// ---- precompute: V^T in mma A-fragment order (m=16 d-rows, k=8 keys) ----
__global__ void swizzle_v_kernel(const float* __restrict__ v) {
    int t = blockIdx.x * blockDim.x + threadIdx.x;   // VFRAG_N threads
    int lane = t & 31;
    int jb   = (t >> 5) & (NJBLK - 1);
    int dt   = (t >> 14) & (NDTILE - 1);
    int h    = t >> 17;
    int g  = lane >> 2;
    int tg = lane & 3;
    int d  = dt * 16 + g;
    int j  = jb * 8 + tg;
    const float* vb = v + (size_t)(h * T_SRC) * HID;
    // A row-major frag: a0=(d, j), a1=(d+8, j), a2=(d, j+4), a3=(d+8, j+4)
    g_vfrag[t] = make_float4(vb[(size_t)j * HID + d],
                             vb[(size_t)j * HID + d + 8],
                             vb[(size_t)(j + 4) * HID + d],
                             vb[(size_t)(j + 4) * HID + d + 8]);
}

__global__ __launch_bounds__(NT, 1)
void tree_attn_r12(const float* __restrict__ q,
                   const float* __restrict__ v,
                   float* __restrict__ out) {
    extern __shared__ char smem_raw[];
    float*    s_sc   = (float*)smem_raw;                     // [QT][T_SRC]
    float*    s_q    = s_sc + W_SC;                          // [QT][HID]
    int*      s_idx  = (int*)(s_q + W_Q);                    // [QT][KTOP]
    float*    s_w    = (float*)(s_idx + W_IDX);              // [QT][KTOP]
    unsigned* s_h3   = (unsigned*)(s_w + W_W);               // [QT][HPAD]
    int*      s_cand = (int*)(s_h3 + W_H3);                  // [QT][CAND_CAP]
    int*      s_c2   = (int*)(s_cand + W_CAND);              // [QT][C2_CAP]
    int*      s_eq   = (int*)(s_c2 + W_C2);                  // [KTOP]
    unsigned* s_ctrl = (unsigned*)(s_eq + W_EQ);             // [W_CTRL]
    float*    s_buf  = (float*)s_h3;                         // [NT] union (sparse AV)
    float*    s_av   = (float*)s_h3;                         // [2][8q][128d] union (dense AV)
    unsigned* s_b3   = s_ctrl;            // [8]
    unsigned* s_ngt3 = s_ctrl + 8;        // [8]
    unsigned* s_gtc  = s_ctrl + 16;       // [8]
    unsigned* s_cc   = s_ctrl + 24;       // [8]
    unsigned* s_ovf  = s_ctrl + 32;       // [8]
    unsigned* s_misc = s_ctrl + 40;       // [8]
    float*    s_inv  = (float*)(s_ctrl + 48);  // [8]
    __shared__ float s_redf[NW];

    const int tile = (NTILES - 1) - blockIdx.x;  // longest rows first
    const int h    = blockIdx.y;
    const int tid  = threadIdx.x;
    const int wid  = tid >> 5;
    const int lane = tid & 31;
    const unsigned lmlt = (1u << lane) - 1u;
    const int qi0  = tile * QT;
    const int n_max = qi0 + QT;
    const bool sparse = (qi0 >= TDENSE);

    const float* vbase = v + (size_t)h * T_SRC * HID;

    for (int d = tid; d < QT * HID; d += NT)
        s_q[d] = q[((size_t)h * T_DST + qi0) * HID + d];
    if (sparse) {
        for (int i = tid; i < QT * HPAD; i += NT) s_h3[i] = 0u;
        if (tid < 8) { s_gtc[tid] = 0u; s_cc[tid] = 0u; s_ovf[tid] = 0u; }
    }
    __syncthreads();

    // ---- B (query) fragments: resident in registers ----
    const int g  = lane >> 2;   // 0..7
    const int tg = lane & 3;
    unsigned bh[16][2], bl[16][2];
    #pragma unroll
    for (int st = 0; st < 16; st++) {
        float x0 = s_q[g * HID + st * 8 + tg];
        float x1 = s_q[g * HID + st * 8 + tg + 4];
        unsigned h0 = tf32_hi_bits(x0);
        unsigned h1 = tf32_hi_bits(x1);
        bh[st][0] = h0;
        bh[st][1] = h1;
        bl[st][0] = __float_as_uint(x0 - __uint_as_float(h0));
        bl[st][1] = __float_as_uint(x1 - __uint_as_float(h1));
    }

    // ---- scores via 3xTF32 mma, in-register hi/lo split, fused histogram ----
    float mx[QT];
    #pragma unroll
    for (int s = 0; s < QT; s++) mx[s] = -CUDART_INF_F;

    const int nblk = (n_max + 15) >> 4;
    for (int blk = wid; blk < nblk; blk += NW) {
        float d0 = 0.f, d1 = 0.f, d2 = 0.f, d3 = 0.f;
        const float4* fk = g_kfrag + ((size_t)(h * NBLK_MAX + blk) * 16) * 32 + lane;
        #pragma unroll
        for (int st = 0; st < 16; st++) {
            float4 a4 = fk[st * 32];
            unsigned a0 = tf32_hi_bits(a4.x), a1 = tf32_hi_bits(a4.y);
            unsigned a2 = tf32_hi_bits(a4.z), a3 = tf32_hi_bits(a4.w);
            unsigned l0 = __float_as_uint(a4.x - __uint_as_float(a0));
            unsigned l1 = __float_as_uint(a4.y - __uint_as_float(a1));
            unsigned l2 = __float_as_uint(a4.z - __uint_as_float(a2));
            unsigned l3 = __float_as_uint(a4.w - __uint_as_float(a3));
            mma_tf32(d0, d1, d2, d3, a0, a1, a2, a3, bh[st][0], bh[st][1]);
            mma_tf32(d0, d1, d2, d3, a0, a1, a2, a3, bl[st][0], bl[st][1]);
            mma_tf32(d0, d1, d2, d3, l0, l1, l2, l3, bh[st][0], bh[st][1]);
        }
        const int kA = blk * 16 + g;
        const int kB = kA + 8;
        const int q0 = tg * 2;
        const int q1 = q0 + 1;
        float v0 = (kA <= qi0 + q0) ? d0 : -CUDART_INF_F;
        float v1 = (kA <= qi0 + q1) ? d1 : -CUDART_INF_F;
        float v2 = (kB <= qi0 + q0) ? d2 : -CUDART_INF_F;
        float v3 = (kB <= qi0 + q1) ? d3 : -CUDART_INF_F;
        s_sc[q0 * T_SRC + kA] = v0;
        s_sc[q1 * T_SRC + kA] = v1;
        s_sc[q0 * T_SRC + kB] = v2;
        s_sc[q1 * T_SRC + kB] = v3;
        mx[q0] = fmaxf(mx[q0], fmaxf(v0, v2));
        mx[q1] = fmaxf(mx[q1], fmaxf(v1, v3));
        if (sparse) {
            atomicAdd(&s_h3[q0 * HPAD + (fkey(v0) >> 24)], 1u);
            atomicAdd(&s_h3[q1 * HPAD + (fkey(v1) >> 24)], 1u);
            atomicAdd(&s_h3[q0 * HPAD + (fkey(v2) >> 24)], 1u);
            atomicAdd(&s_h3[q1 * HPAD + (fkey(v3) >> 24)], 1u);
        }
    }
    __syncthreads();

    float m[QT];
    #pragma unroll
    for (int s = 0; s < QT; s++) m[s] = block_max(mx[s], s_redf);

    if (!sparse) {
        // ================= dense causal softmax =================
        float psum[QT];
        #pragma unroll
        for (int s = 0; s < QT; s++) psum[s] = 0.0f;
        for (int j = tid; j < n_max; j += NT) {
            #pragma unroll
            for (int s = 0; s < QT; s++) {
                float sc = s_sc[s * T_SRC + j];
                float e = (j <= qi0 + s) ? __expf(sc - m[s]) : 0.0f;
                s_sc[s * T_SRC + j] = e;
                psum[s] += e;
            }
        }
        #pragma unroll
        for (int s = 0; s < QT; s++) {
            float iv = 1.0f / block_sum(psum[s], s_redf);
            if (tid == 0) s_inv[s] = iv;
        }
        // block_sum ends with __syncthreads: s_sc (P) and s_inv are visible

        // ---- dense AV via 3xTF32 mma on precomputed V^T fragments ----
        {
            const int dt = wid & 7;          // d-tile 0..7
            const int jh = wid >> 3;         // j-half 0..1
            const int jchunks = n_max >> 3;  // n_max divisible by 8
            float e0 = 0.f, e1 = 0.f, e2 = 0.f, e3 = 0.f;
            const float4* fv = g_vfrag + ((size_t)((h * NDTILE + dt) * NJBLK)) * 32 + lane;
            for (int c = jh; c < jchunks; c += 2) {
                float4 a4 = fv[c * 32];
                unsigned a0 = tf32_hi_bits(a4.x), a1 = tf32_hi_bits(a4.y);
                unsigned a2 = tf32_hi_bits(a4.z), a3 = tf32_hi_bits(a4.w);
                unsigned l0 = __float_as_uint(a4.x - __uint_as_float(a0));
                unsigned l1 = __float_as_uint(a4.y - __uint_as_float(a1));
                unsigned l2 = __float_as_uint(a4.z - __uint_as_float(a2));
                unsigned l3 = __float_as_uint(a4.w - __uint_as_float(a3));
                float p0 = s_sc[g * T_SRC + c * 8 + tg];
                float p1 = s_sc[g * T_SRC + c * 8 + tg + 4];
                unsigned ph0 = tf32_hi_bits(p0);
                unsigned ph1 = tf32_hi_bits(p1);
                unsigned pl0 = __float_as_uint(p0 - __uint_as_float(ph0));
                unsigned pl1 = __float_as_uint(p1 - __uint_as_float(ph1));
                mma_tf32(e0, e1, e2, e3, a0, a1, a2, a3, ph0, ph1);  // hi*hi
                mma_tf32(e0, e1, e2, e3, l0, l1, l2, l3, ph0, ph1);  // lo*hi
                mma_tf32(e0, e1, e2, e3, a0, a1, a2, a3, pl0, pl1);  // hi*lo
            }
            // D frag: rows = d (dt*16+g, +8), cols = q (tg*2, +1); layout s_av[jh][q][d]
            int base = jh * 1024 + (tg * 2) * HID + dt * 16 + g;
            s_av[base]           = e0;
            s_av[base + HID]     = e1;
            s_av[base + 8]       = e2;
            s_av[base + HID + 8] = e3;
        }
        __syncthreads();
        #pragma unroll
        for (int i = tid; i < QT * HID; i += NT) {
            int qq = i >> 7;
            out[((size_t)h * T_DST + qi0 + qq) * HID + (i & (HID - 1))] =
                (s_av[i] + s_av[1024 + i]) * s_inv[qq];
        }
    } else {
        // ================= sparse: exact top-128 =================
        const int bound = ((n_max + NT - 1) / NT) * NT;

        // ---- per-warp bin scan (warps 0..7); histogram already built ----
        if (wid < QT) {
            const int s = wid;
            unsigned gg = 0;
            #pragma unroll
            for (int b = 0; b < 8; b++) gg += s_h3[s * HPAD + lane * 8 + b];
            unsigned run = gg;
            #pragma unroll
            for (int o = 1; o < 32; o <<= 1) {
                unsigned u = __shfl_down_sync(0xFFFFFFFFu, run, o);
                if (lane + o < 32) run += u;
            }
            unsigned S = run - gg;
            int found = (run >= KTOP && S < KTOP);
            unsigned blb = 0, acc2 = 0;
            if (found) {
                acc2 = S;
                #pragma unroll 1
                for (int b = 7; b >= 0; b--) {
                    unsigned c = s_h3[s * HPAD + lane * 8 + b];
                    if (acc2 + c >= KTOP) { blb = lane * 8 + b; break; }
                    acc2 += c;
                }
            }
            unsigned fmask = __ballot_sync(0xFFFFFFFFu, found);
            int flane = __ffs(fmask) - 1;
            blb  = __shfl_sync(0xFFFFFFFFu, blb, flane);
            acc2 = __shfl_sync(0xFFFFFFFFu, acc2, flane);
            if (lane == 0) { s_b3[s] = blb; s_ngt3[s] = acc2; }
        }
        __syncthreads();

        // ---- combined compact sweep ----
        for (int j = tid; j < bound; j += NT) {
            #pragma unroll
            for (int s = 0; s < QT; s++) {
                unsigned bin = 257u;
                if (j < n_max) bin = fkey(s_sc[s * T_SRC + j]) >> 24;
                const unsigned b3v = s_b3[s];
                bool gt = (bin > b3v) && (bin <= 255u);
                bool eq = (bin == b3v);
                unsigned mg = __ballot_sync(0xFFFFFFFFu, gt);
                unsigned me = __ballot_sync(0xFFFFFFFFu, eq);
                unsigned baseg = 0, basee = 0;
                if (mg && lane == (unsigned)(__ffs(mg) - 1))
                    baseg = atomicAdd(&s_gtc[s], (unsigned)__popc(mg));
                if (me && lane == (unsigned)(__ffs(me) - 1))
                    basee = atomicAdd(&s_cc[s], (unsigned)__popc(me));
                if (mg) {
                    baseg = __shfl_sync(0xFFFFFFFFu, baseg, __ffs(mg) - 1);
                    if (gt) s_idx[s * KTOP + baseg + __popc(mg & lmlt)] = j;
                }
                if (me) {
                    basee = __shfl_sync(0xFFFFFFFFu, basee, __ffs(me) - 1);
                    if (eq) {
                        unsigned p = basee + __popc(me & lmlt);
                        if (p < CAND_CAP) s_cand[s * CAND_CAP + p] = j;
                    }
                }
            }
        }
        __syncthreads();

        // ---- per-warp refinement (warps 0..7) ----
        if (wid < QT) {
            const int s = wid;
            const float* sc = s_sc + s * T_SRC;
            int nc = (int)s_cc[s];
            unsigned ngt = s_ngt3[s];
            bool ok = (nc <= CAND_CAP);
            int cur = 0;
            int* lists[2] = { s_cand + s * CAND_CAP, s_c2 + s * C2_CAP };
            const int caps[2] = { CAND_CAP, C2_CAP };

            #pragma unroll 1
            for (int lvl = 2; lvl >= 0 && ok; lvl--) {
                const int shift = lvl * 8;
                for (int b = lane; b < 257; b += 32) s_h3[s * HPAD + b] = 0u;
                __syncwarp();
                const int rb = (nc + 31) & ~31;
                for (int i = lane; i < rb; i += 32) {
                    unsigned bin = 256u;
                    if (i < nc) bin = (fkey(sc[lists[cur][i]]) >> shift) & 255u;
                    unsigned peers = __match_any_sync(0xFFFFFFFFu, bin);
                    if ((__ffs(peers) - 1) == lane)
                        s_h3[s * HPAD + bin] += (unsigned)__popc(peers);
                }
                __syncwarp();
                unsigned gg = 0;
                #pragma unroll
                for (int b = 0; b < 8; b++) gg += s_h3[s * HPAD + lane * 8 + b];
                unsigned run = gg;
                #pragma unroll
                for (int o = 1; o < 32; o <<= 1) {
                    unsigned u = __shfl_down_sync(0xFFFFFFFFu, run, o);
                    if (lane + o < 32) run += u;
                }
                unsigned S = run - gg;
                int found = (ngt + run >= KTOP && ngt + S < KTOP);
                unsigned blb = 0;
                if (found) {
                    unsigned acc2 = ngt + S;
                    #pragma unroll 1
                    for (int b = 7; b >= 0; b--) {
                        unsigned c = s_h3[s * HPAD + lane * 8 + b];
                        if (acc2 + c >= KTOP) { blb = lane * 8 + b; break; }
                        acc2 += c;
                    }
                }
                unsigned fmask = __ballot_sync(0xFFFFFFFFu, found);
                int flane = __ffs(fmask) - 1;
                blb = __shfl_sync(0xFFFFFFFFu, blb, flane);
                const int dst = cur ^ 1;
                int* dl = lists[dst];
                const int dcap = caps[dst];
                unsigned wg = ngt, we = 0;
                for (int i = lane; i < rb; i += 32) {
                    unsigned bin = 256u; int j = 0;
                    if (i < nc) { j = lists[cur][i]; bin = (fkey(sc[j]) >> shift) & 255u; }
                    bool gt = (bin > blb) && (bin <= 255u);
                    bool eq = (bin == blb);
                    unsigned mg = __ballot_sync(0xFFFFFFFFu, gt);
                    unsigned me = __ballot_sync(0xFFFFFFFFu, eq);
                    if (gt) s_idx[s * KTOP + wg + __popc(mg & lmlt)] = j;
                    if (eq) {
                        unsigned p = we + __popc(me & lmlt);
                        if ((int)p < dcap) dl[p] = j;
                    }
                    wg += __popc(mg); we += __popc(me);
                }
                ngt = wg;
                nc = (int)we;
                cur = dst;
                if (nc > dcap) ok = false;
                __syncwarp();
            }
            if (ok) {
                const int need = KTOP - (int)ngt;
                const int* tl = lists[cur];
                for (int i = lane; i < nc; i += 32) {
                    int ji = tl[i];
                    int rank = 0;
                    for (int m2 = 0; m2 < nc; m2++) rank += (tl[m2] < ji);
                    if (rank < need) s_idx[s * KTOP + (int)ngt + rank] = ji;
                }
            } else if (lane == 0) {
                s_ovf[s] = 1u;
            }
        }
        __syncthreads();

        // ---- rare fallback: full 4-level radix ----
        unsigned ovf_any = 0;
        #pragma unroll
        for (int s = 0; s < QT; s++) ovf_any |= s_ovf[s];
        if (ovf_any) {
            #pragma unroll 1
            for (int s = 0; s < QT; s++) {
                if (!s_ovf[s]) continue;
                const float* sc = s_sc + s * T_SRC;
                unsigned prefix = 0, ngt = 0;
                #pragma unroll 1
                for (int level = 3; level >= 0; level--) {
                    for (int b = tid; b < 257; b += NT) s_h3[b] = 0u;
                    __syncthreads();
                    const unsigned shift = level * 8;
                    const unsigned pmask = (level == 3) ? 0u : (0xFFFFFFFFu << (shift + 8));
                    for (int j = tid; j < bound; j += NT) {
                        unsigned bin = 256u;
                        if (j < n_max) {
                            unsigned key = fkey(sc[j]);
                            if ((key & pmask) == prefix) bin = (key >> shift) & 0xFFu;
                        }
                        unsigned peers = __match_any_sync(0xFFFFFFFFu, bin);
                        if ((__ffs(peers) - 1) == lane)
                            atomicAdd(&s_h3[bin], (unsigned)__popc(peers));
                    }
                    __syncthreads();
                    if (tid < 32) {
                        unsigned gg = 0;
                        #pragma unroll
                        for (int b = 0; b < 8; b++) gg += s_h3[tid * 8 + b];
                        unsigned run = gg;
                        #pragma unroll
                        for (int o = 1; o < 32; o <<= 1) {
                            unsigned u = __shfl_down_sync(0xFFFFFFFFu, run, o);
                            if (tid + o < 32) run += u;
                        }
                        unsigned S = run - gg;
                        if (ngt + run >= KTOP && ngt + S < KTOP) {
                            unsigned acc2 = ngt + S;
                            #pragma unroll 1
                            for (int b = 7; b >= 0; b--) {
                                unsigned c = s_h3[tid * 8 + b];
                                if (acc2 + c >= KTOP) {
                                    s_misc[0] = prefix | ((unsigned)(tid * 8 + b) << shift);
                                    s_misc[1] = acc2;
                                    break;
                                }
                                acc2 += c;
                            }
                        }
                    }
                    __syncthreads();
                    prefix = s_misc[0];
                    ngt = s_misc[1];
                    __syncthreads();
                }
                const unsigned t_key = prefix;
                if (tid == 0) { s_misc[2] = 0u; s_misc[3] = 0u; }
                __syncthreads();
                for (int j = tid; j < n_max; j += NT) {
                    unsigned key = fkey(sc[j]);
                    if (key > t_key) {
                        unsigned p = atomicAdd(&s_misc[2], 1u);
                        s_idx[s * KTOP + p] = j;
                    } else if (key == t_key) {
                        unsigned p = atomicAdd(&s_misc[3], 1u);
                        if (p < KTOP) s_eq[p] = j;
                    }
                }
                __syncthreads();
                const int neq = (int)s_misc[3];
                const int need = KTOP - (int)ngt;
                if (need < neq && tid == 0) {
                    int c = (neq < KTOP) ? neq : KTOP;
                    for (int a = 0; a < need; a++) {
                        int mb = a;
                        for (int b = a + 1; b < c; b++)
                            if (s_eq[b] < s_eq[mb]) mb = b;
                        int t2 = s_eq[a]; s_eq[a] = s_eq[mb]; s_eq[mb] = t2;
                    }
                }
                __syncthreads();
                for (int a = tid; a < need; a += NT) s_idx[s * KTOP + (int)ngt + a] = s_eq[a];
                __syncthreads();
            }
        }

        // ---- per-warp softmax weights (warps 0..7) ----
        if (wid < QT) {
            const int s = wid;
            float psum = 0.0f;
            #pragma unroll
            for (int i = 0; i < KTOP / 32; i++) {
                int a = lane + i * 32;
                float e = __expf(s_sc[s * T_SRC + s_idx[s * KTOP + a]] - m[s]);
                s_w[s * KTOP + a] = e;
                psum += e;
            }
            #pragma unroll
            for (int o = 16; o; o >>= 1) psum += __shfl_xor_sync(0xFFFFFFFFu, psum, o);
            if (lane == 0) s_inv[s] = 1.0f / psum;
        }
        __syncthreads();

        // ---- AV over gathered rows ----
        const int d  = tid & (HID - 1);
        const int qr = tid >> 7;   // 0..3
        float acc[QT];
        #pragma unroll
        for (int s = 0; s < QT; s++) acc[s] = 0.0f;
        for (int a = qr; a < KTOP; a += 4) {
            #pragma unroll
            for (int s = 0; s < QT; s++) {
                int j = s_idx[s * KTOP + a];
                acc[s] = fmaf(s_w[s * KTOP + a], vbase[(size_t)j * HID + d], acc[s]);
            }
        }
        #pragma unroll
        for (int s = 0; s < QT; s++) {
            __syncthreads();
            s_buf[tid] = acc[s];
            __syncthreads();
            if (tid < HID)
                out[((size_t)h * T_DST + qi0 + s) * HID + tid] =
                    (s_buf[tid] + s_buf[tid + HID] + s_buf[tid + 2*HID] + s_buf[tid + 3*HID]) * s_inv[s];
        }
    }
}

extern "C" void kernel_launch(void* const* d_in, const int* in_sizes, int n_in,
                              void* d_out, int out_size) {
    const float* q = (const float*)d_in[0];
    const float* k = (const float*)d_in[1];
    const float* v = (const float*)d_in[2];
    float* out = (float*)d_out;

    swizzle_k_kernel<<<KFRAG_N / 256, 256>>>(k);
    swizzle_v_kernel<<<VFRAG_N / 256, 256>>>(v);

    cudaFuncSetAttribute(tree_attn_r12,
                         cudaFuncAttributeMaxDynamicSharedMemorySize, DYN_BYTES);

    dim3 grid(NTILES, NHEADS);
    tree_attn_r12<<<grid, NT, DYN_BYTES>>>(q, v, out);
}